// round 9
// baseline (speedup 1.0000x reference)
#include <cuda_runtime.h>
#include <math.h>
#include <stdint.h>

#define B_ 2
#define L_ 1024
#define D_ 768
#define H_ 12
#define HD_ 64
#define FF_ 3072
#define V_ 32000
#define NL_ 2
#define TOK_BOS 1
#define TOK_SEP 2
#define WIN_ 512
#define EPS_ 1e-5f
#define M_ (B_ * L_) /* 2048 rows */

// ---------------- scratch (static device globals; no allocation) ------------
__device__ float g_x[M_ * D_];
__device__ float g_qkv[M_ * 3 * D_];
__device__ int   g_seg[B_ * L_];
__device__ int   g_gkey[B_ * L_];
__device__ int   g_valid[B_ * L_];

// fragment-major tf32 operand buffers (uint32 = tf32 bits)
__device__ unsigned g_ht[M_ * D_];
__device__ unsigned g_yt[M_ * D_];
__device__ unsigned g_ft[M_ * FF_];
__device__ unsigned g_wqt[NL_ * 3 * D_ * D_];
__device__ unsigned g_wot[NL_ * D_ * D_];
__device__ unsigned g_w1t[NL_ * FF_ * D_];
__device__ unsigned g_w2t[NL_ * D_ * FF_];
__device__ unsigned g_wht[V_ * D_];

// ---------------- helpers ----------------------------------------------------
__device__ __forceinline__ unsigned f2tf(float x) {
    unsigned r;
    asm("cvt.rna.tf32.f32 %0, %1;" : "=r"(r) : "f"(x));
    return r;
}
__device__ __forceinline__ uint32_t smem_u32(const void* p) {
    uint32_t a;
    asm("{ .reg .u64 t; cvta.to.shared.u64 t, %1; cvt.u32.u64 %0, t; }" : "=r"(a) : "l"(p));
    return a;
}
__device__ __forceinline__ void cpa16(uint32_t s, const void* g) {
    asm volatile("cp.async.cg.shared.global [%0], [%1], 16;" :: "r"(s), "l"(g));
}
#define CP_COMMIT() asm volatile("cp.async.commit_group;" ::: "memory")
#define CP_WAIT1()  asm volatile("cp.async.wait_group 1;" ::: "memory")
#define CP_WAIT0()  asm volatile("cp.async.wait_group 0;" ::: "memory")

__device__ __forceinline__ void mma8(float* c, const unsigned* a, const unsigned* b) {
    asm volatile(
        "mma.sync.aligned.m16n8k8.row.col.f32.tf32.tf32.f32 "
        "{%0,%1,%2,%3}, {%4,%5,%6,%7}, {%8,%9}, {%0,%1,%2,%3};\n"
        : "+f"(c[0]), "+f"(c[1]), "+f"(c[2]), "+f"(c[3])
        : "r"(a[0]), "r"(a[1]), "r"(a[2]), "r"(a[3]), "r"(b[0]), "r"(b[1]));
}

// fragment-major indices (see R6): 1024 uints per (128row x 8k) slab
__device__ __forceinline__ size_t a_idx(int Kd, int m, int c) {
    return ((size_t)(m >> 7) * (Kd >> 3) + (c >> 3)) * 1024
         + (size_t)(((m & 127) >> 4) * 128)
         + (((m & 7) * 4 + (c & 3)) << 2)
         + ((m & 15) >> 3) + 2 * ((c & 7) >> 2);
}
__device__ __forceinline__ size_t b_idx(int Kd, int n, int k) {
    return ((size_t)(n >> 7) * (Kd >> 3) + (k >> 3)) * 1024
         + (size_t)(((n & 127) >> 4) * 128)
         + (((n & 7) * 4 + (k & 3)) << 2)
         + ((k & 7) >> 2) + 2 * ((n & 15) >> 3);
}

// ---------------- embedding -------------------------------------------------
__global__ void k_embed(const int* __restrict__ tokens, const int* __restrict__ types,
                        const float* __restrict__ tok_emb, const float* __restrict__ type_emb,
                        const float* __restrict__ pos_emb) {
    int idx = blockIdx.x * blockDim.x + threadIdx.x;
    if (idx >= M_ * D_) return;
    int d = idx % D_;
    int bl = idx / D_;
    int l = bl % L_;
    g_x[idx] = tok_emb[(size_t)tokens[bl] * D_ + d]
             + type_emb[(size_t)types[bl] * D_ + d]
             + pos_emb[(size_t)l * D_ + d];
}

// ---------------- mask metadata ----------------------------------------------
__global__ void k_maskprep(const int* __restrict__ tokens, const int* __restrict__ attn_mask) {
    int b = threadIdx.x;
    if (b >= B_) return;
    int seg = 0;
    for (int l = 0; l < L_; l++) {
        int i = b * L_ + l;
        int va = attn_mask[i] != 0;
        int tok = tokens[i];
        int is_sep = (tok == TOK_SEP) && va;
        seg += is_sep;
        g_seg[i] = seg;
        g_gkey[i] = (((tok == TOK_BOS) && va) || is_sep) ? 1 : 0;
        g_valid[i] = va;
    }
}

// ---------------- weight conversion: fp32 [N,K] -> B-tiled tf32 -------------
__global__ void k_cvt_w(const float* __restrict__ W, unsigned* __restrict__ out,
                        int N, int K) {
    int idx = blockIdx.x * blockDim.x + threadIdx.x;
    if (idx >= N * K) return;
    int n = idx / K, k = idx % K;
    out[b_idx(K, n, k)] = f2tf(W[idx]);
}

// ---------------- layernorm -> A-tiled tf32 ----------------------------------
__global__ __launch_bounds__(256)
void k_ln_t(const float* __restrict__ x, const float* __restrict__ sc,
            const float* __restrict__ bi, unsigned* __restrict__ out) {
    int row = blockIdx.x;
    const float* xr = x + (size_t)row * D_;
    int t = threadIdx.x;
    float v0 = xr[t], v1 = xr[t + 256], v2 = xr[t + 512];
    float s = v0 + v1 + v2;
    float ss = v0 * v0 + v1 * v1 + v2 * v2;
    __shared__ float rs[8], rq[8];
#pragma unroll
    for (int o = 16; o > 0; o >>= 1) {
        s  += __shfl_xor_sync(0xffffffffu, s, o);
        ss += __shfl_xor_sync(0xffffffffu, ss, o);
    }
    if ((t & 31) == 0) { rs[t >> 5] = s; rq[t >> 5] = ss; }
    __syncthreads();
    if (t < 32) {
        float a = (t < 8) ? rs[t] : 0.f;
        float q = (t < 8) ? rq[t] : 0.f;
#pragma unroll
        for (int o = 4; o > 0; o >>= 1) {
            a += __shfl_xor_sync(0xffffffffu, a, o);
            q += __shfl_xor_sync(0xffffffffu, q, o);
        }
        if (t == 0) { rs[0] = a; rq[0] = q; }
    }
    __syncthreads();
    float mean = rs[0] * (1.0f / D_);
    float var  = rq[0] * (1.0f / D_) - mean * mean;
    float inv = rsqrtf(var + EPS_);
    out[a_idx(D_, row, t)]       = f2tf((v0 - mean) * inv * sc[t]       + bi[t]);
    out[a_idx(D_, row, t + 256)] = f2tf((v1 - mean) * inv * sc[t + 256] + bi[t + 256]);
    out[a_idx(D_, row, t + 512)] = f2tf((v2 - mean) * inv * sc[t + 512] + bi[t + 512]);
}

// ---------------- TF32 MMA GEMM: 128x128 tile, 4 warps, warp 64x64 ----------
// BK=32, 3-stage cp.async. Operand demand 128B/MMA -> 50% tensor ceiling.
template <int DOGELU, int OUTT>
__global__ void __launch_bounds__(128, 2)
k_mma_t(const unsigned* __restrict__ At, const unsigned* __restrict__ Bt,
        float* __restrict__ C, unsigned* __restrict__ Ct,
        int N, int K, int KtOut,
        const float* __restrict__ bias, const float* __restrict__ resid) {
    extern __shared__ uint4 sm4[];   // [3][2048] uint4 = 96KB
    const int bm = blockIdx.x * 128, bn = blockIdx.y * 128;
    const int tid = threadIdx.x;
    const int lane = tid & 31, warp = tid >> 5;
    const int wm = (warp & 1) * 64, wn = (warp >> 1) * 64;
    const int gid = lane >> 2, cid = lane & 3;
    const int K8 = K >> 3;

    const uint4* gA = (const uint4*)(At + ((size_t)blockIdx.x * K8) * 1024);
    const uint4* gB = (const uint4*)(Bt + ((size_t)blockIdx.y * K8) * 1024);
    const uint32_t s0 = smem_u32(&sm4[0]);
    const uint32_t sAld = s0 + tid * 16;
    const uint32_t sBld = s0 + 16384 + tid * 16;

    float acc[4][8][4];
#pragma unroll
    for (int i = 0; i < 4; i++)
#pragma unroll
        for (int j = 0; j < 8; j++)
#pragma unroll
            for (int r = 0; r < 4; r++) acc[i][j][r] = 0.f;

    const int nk = K >> 5;
    // prologue: stages 0, 1 (A 1024 uint4 + B 1024 uint4 per kt; 128 threads x 8)
#pragma unroll
    for (int st = 0; st < 2; st++) {
        const uint4* gAn = gA + st * 1024;
        const uint4* gBn = gB + st * 1024;
        uint32_t off = st * 32768;
#pragma unroll
        for (int i = 0; i < 8; i++) {
            cpa16(sAld + off + i * 2048, gAn + i * 128 + tid);
            cpa16(sBld + off + i * 2048, gBn + i * 128 + tid);
        }
        CP_COMMIT();
    }

    int s = 0;
    for (int kt = 0; kt < nk; kt++) {
        if (kt < nk - 1) { CP_WAIT1(); } else { CP_WAIT0(); }
        __syncthreads();
        if (kt + 2 < nk) {
            const uint4* gAn = gA + (kt + 2) * 1024;
            const uint4* gBn = gB + (kt + 2) * 1024;
            int sn = s + 2; if (sn >= 3) sn -= 3;
            uint32_t off = sn * 32768;
#pragma unroll
            for (int i = 0; i < 8; i++) {
                cpa16(sAld + off + i * 2048, gAn + i * 128 + tid);
                cpa16(sBld + off + i * 2048, gBn + i * 128 + tid);
            }
            CP_COMMIT();
        }
        const uint4* sa = &sm4[s * 2048];
        const uint4* sb = sa + 1024;
#pragma unroll
        for (int ks = 0; ks < 4; ks++) {
            uint4 af[4];
#pragma unroll
            for (int mi = 0; mi < 4; mi++)
                af[mi] = sa[ks * 256 + ((wm >> 4) + mi) * 32 + lane];
            uint4 bq[4];
#pragma unroll
            for (int nt = 0; nt < 4; nt++)
                bq[nt] = sb[ks * 256 + ((wn >> 4) + nt) * 32 + lane];
            unsigned bf[8][2] = {
                {bq[0].x, bq[0].y}, {bq[0].z, bq[0].w},
                {bq[1].x, bq[1].y}, {bq[1].z, bq[1].w},
                {bq[2].x, bq[2].y}, {bq[2].z, bq[2].w},
                {bq[3].x, bq[3].y}, {bq[3].z, bq[3].w}};
#pragma unroll
            for (int mi = 0; mi < 4; mi++)
#pragma unroll
                for (int ni = 0; ni < 8; ni++)
                    mma8(acc[mi][ni], (const unsigned*)&af[mi], bf[ni]);
        }
        if (++s == 3) s = 0;
    }

    // epilogue
#pragma unroll
    for (int mi = 0; mi < 4; mi++) {
        int r0 = bm + wm + mi * 16 + gid;
#pragma unroll
        for (int ni = 0; ni < 8; ni++) {
            int c0 = bn + wn + ni * 8 + 2 * cid;
            float v00 = acc[mi][ni][0], v01 = acc[mi][ni][1];
            float v10 = acc[mi][ni][2], v11 = acc[mi][ni][3];
            if (bias) {
                float b0v = bias[c0], b1v = bias[c0 + 1];
                v00 += b0v; v01 += b1v; v10 += b0v; v11 += b1v;
            }
            if (resid) {
                const float* rr0 = resid + (size_t)r0 * N + c0;
                const float* rr1 = resid + (size_t)(r0 + 8) * N + c0;
                v00 += rr0[0]; v01 += rr0[1]; v10 += rr1[0]; v11 += rr1[1];
            }
            if (DOGELU) {
                v00 = 0.5f * v00 * (1.0f + erff(v00 * 0.70710678118654752f));
                v01 = 0.5f * v01 * (1.0f + erff(v01 * 0.70710678118654752f));
                v10 = 0.5f * v10 * (1.0f + erff(v10 * 0.70710678118654752f));
                v11 = 0.5f * v11 * (1.0f + erff(v11 * 0.70710678118654752f));
            }
            if (OUTT == 0) {
                *(float2*)&C[(size_t)r0 * N + c0]       = make_float2(v00, v01);
                *(float2*)&C[(size_t)(r0 + 8) * N + c0] = make_float2(v10, v11);
            } else {
                Ct[a_idx(KtOut, r0, c0)]         = f2tf(v00);
                Ct[a_idx(KtOut, r0, c0 + 1)]     = f2tf(v01);
                Ct[a_idx(KtOut, r0 + 8, c0)]     = f2tf(v10);
                Ct[a_idx(KtOut, r0 + 8, c0 + 1)] = f2tf(v11);
            }
        }
    }
}

// ---------------- fused flash attention (per b,h, 64-query tile) ------------
__global__ __launch_bounds__(256)
void k_attn(const float* __restrict__ qkv) {
    extern __shared__ float sm[];
    float* Qs = sm;
    float* Ks = sm + 64 * 65;
    float* Vs = sm + 2 * 64 * 65;
    float* Ps = sm + 2 * 64 * 65 + 64 * 64;
    __shared__ int sSeg[64], sGk[64], sVa[64];

    const int bh = blockIdx.y;
    const int b = bh / H_, h = bh % H_;
    const int i0 = (gridDim.x - 1 - blockIdx.x) * 64;
    const int t = threadIdx.x;
    const int tm = (t >> 4) * 4, tn = (t & 15) * 4;

    const float* qb = qkv + (size_t)(b * L_ + i0) * (3 * D_) + h * HD_;
    for (int idx = t; idx < 64 * 64; idx += 256) {
        int r = idx >> 6, c = idx & 63;
        Qs[r * 65 + c] = qb[(size_t)r * (3 * D_) + c];
    }
    int gi[4], si[4];
#pragma unroll
    for (int i = 0; i < 4; i++) {
        gi[i] = i0 + tm + i;
        si[i] = g_seg[b * L_ + gi[i]];
    }

    float m[4] = {-1e30f, -1e30f, -1e30f, -1e30f};
    float lsum[4] = {0.f, 0.f, 0.f, 0.f};
    float o[4][4] = {};

    for (int j0 = 0; j0 <= i0; j0 += 64) {
        __syncthreads();
        const float* kb = qkv + (size_t)(b * L_ + j0) * (3 * D_) + D_ + h * HD_;
        const float* vb = qkv + (size_t)(b * L_ + j0) * (3 * D_) + 2 * D_ + h * HD_;
        for (int idx = t; idx < 64 * 64; idx += 256) {
            int r = idx >> 6, c = idx & 63;
            Ks[r * 65 + c] = kb[(size_t)r * (3 * D_) + c];
            Vs[r * 64 + c] = vb[(size_t)r * (3 * D_) + c];
        }
        if (t < 64) {
            int gj = b * L_ + j0 + t;
            sSeg[t] = g_seg[gj];
            sGk[t]  = g_gkey[gj];
            sVa[t]  = g_valid[gj];
        }
        __syncthreads();

        float s[4][4] = {};
#pragma unroll 8
        for (int d = 0; d < 64; d++) {
            float q[4], k[4];
#pragma unroll
            for (int i = 0; i < 4; i++) { q[i] = Qs[(tm + i) * 65 + d]; k[i] = Ks[(tn + i) * 65 + d]; }
#pragma unroll
            for (int i = 0; i < 4; i++)
#pragma unroll
                for (int j = 0; j < 4; j++) s[i][j] += q[i] * k[j];
        }
#pragma unroll
        for (int i = 0; i < 4; i++)
#pragma unroll
            for (int j = 0; j < 4; j++) {
                int gj = j0 + tn + j;
                bool allowed = (gj <= gi[i]) && sVa[tn + j] &&
                               (sSeg[tn + j] == si[i] || sGk[tn + j] || (gi[i] - gj) <= WIN_);
                s[i][j] = allowed ? s[i][j] * 0.125f : -1e30f;
            }
#pragma unroll
        for (int i = 0; i < 4; i++) {
            float rm = fmaxf(fmaxf(s[i][0], s[i][1]), fmaxf(s[i][2], s[i][3]));
#pragma unroll
            for (int off = 8; off > 0; off >>= 1)
                rm = fmaxf(rm, __shfl_xor_sync(0xffffffffu, rm, off));
            float mn = fmaxf(m[i], rm);
            float alpha = __expf(m[i] - mn);
            m[i] = mn;
            float p0 = (s[i][0] > -1e29f) ? __expf(s[i][0] - mn) : 0.f;
            float p1 = (s[i][1] > -1e29f) ? __expf(s[i][1] - mn) : 0.f;
            float p2 = (s[i][2] > -1e29f) ? __expf(s[i][2] - mn) : 0.f;
            float p3 = (s[i][3] > -1e29f) ? __expf(s[i][3] - mn) : 0.f;
            float rsm = p0 + p1 + p2 + p3;
#pragma unroll
            for (int off = 8; off > 0; off >>= 1)
                rsm += __shfl_xor_sync(0xffffffffu, rsm, off);
            lsum[i] = lsum[i] * alpha + rsm;
#pragma unroll
            for (int j = 0; j < 4; j++) o[i][j] *= alpha;
            Ps[(tm + i) * 65 + tn + 0] = p0;
            Ps[(tm + i) * 65 + tn + 1] = p1;
            Ps[(tm + i) * 65 + tn + 2] = p2;
            Ps[(tm + i) * 65 + tn + 3] = p3;
        }
        __syncthreads();
#pragma unroll 4
        for (int jj = 0; jj < 64; jj++) {
            float pr[4], vv[4];
#pragma unroll
            for (int i = 0; i < 4; i++) { pr[i] = Ps[(tm + i) * 65 + jj]; vv[i] = Vs[jj * 64 + tn + i]; }
#pragma unroll
            for (int i = 0; i < 4; i++)
#pragma unroll
                for (int j = 0; j < 4; j++) o[i][j] += pr[i] * vv[j];
        }
    }
#pragma unroll
    for (int i = 0; i < 4; i++) {
        float inv = 1.0f / lsum[i];
        int mrow = b * L_ + gi[i];
#pragma unroll
        for (int j = 0; j < 4; j++)
            g_yt[a_idx(D_, mrow, h * HD_ + tn + j)] = f2tf(o[i][j] * inv);
    }
}

// ---------------- host side --------------------------------------------------
#define GEMM_SMEM_ 98304
#define ATTN_SMEM_ 66304

static void gemm_t(const unsigned* At, const unsigned* Bt, float* C, unsigned* Ct,
                   int N, int K, int ktout, const float* bias, const float* resid,
                   bool gelu_tiled) {
    dim3 grid(M_ / 128, N / 128);
    if (gelu_tiled)
        k_mma_t<1, 1><<<grid, 128, GEMM_SMEM_>>>(At, Bt, C, Ct, N, K, ktout, bias, resid);
    else
        k_mma_t<0, 0><<<grid, 128, GEMM_SMEM_>>>(At, Bt, C, Ct, N, K, ktout, bias, resid);
}

extern "C" void kernel_launch(void* const* d_in, const int* in_sizes, int n_in,
                              void* d_out, int out_size) {
    const int*   tokens    = (const int*)d_in[0];
    const int*   types     = (const int*)d_in[1];
    const int*   attn_mask = (const int*)d_in[2];
    const float* tok_emb   = (const float*)d_in[3];
    const float* type_emb  = (const float*)d_in[4];
    const float* pos_emb   = (const float*)d_in[5];
    const float* qkv_w     = (const float*)d_in[6];
    const float* out_w     = (const float*)d_in[7];
    const float* ln1_s     = (const float*)d_in[8];
    const float* ln1_b     = (const float*)d_in[9];
    const float* ln2_s     = (const float*)d_in[10];
    const float* ln2_b     = (const float*)d_in[11];
    const float* ff_w1     = (const float*)d_in[12];
    const float* ff_b1     = (const float*)d_in[13];
    const float* ff_w2     = (const float*)d_in[14];
    const float* ff_b2     = (const float*)d_in[15];
    const float* lnf_s     = (const float*)d_in[16];
    const float* lnf_b     = (const float*)d_in[17];
    const float* head_w    = (const float*)d_in[18];
    float* out = (float*)d_out;

    cudaFuncSetAttribute(k_mma_t<0, 0>, cudaFuncAttributeMaxDynamicSharedMemorySize, GEMM_SMEM_);
    cudaFuncSetAttribute(k_mma_t<1, 1>, cudaFuncAttributeMaxDynamicSharedMemorySize, GEMM_SMEM_);
    cudaFuncSetAttribute(k_attn, cudaFuncAttributeMaxDynamicSharedMemorySize, ATTN_SMEM_);

    float *x, *qkv;
    unsigned *ht, *yt, *ft, *wqt, *wot, *w1t, *w2t, *wht;
    cudaGetSymbolAddress((void**)&x, g_x);
    cudaGetSymbolAddress((void**)&qkv, g_qkv);
    cudaGetSymbolAddress((void**)&ht, g_ht);
    cudaGetSymbolAddress((void**)&yt, g_yt);
    cudaGetSymbolAddress((void**)&ft, g_ft);
    cudaGetSymbolAddress((void**)&wqt, g_wqt);
    cudaGetSymbolAddress((void**)&wot, g_wot);
    cudaGetSymbolAddress((void**)&w1t, g_w1t);
    cudaGetSymbolAddress((void**)&w2t, g_w2t);
    cudaGetSymbolAddress((void**)&wht, g_wht);

    for (int l = 0; l < NL_; l++) {
        k_cvt_w<<<(3 * D_ * D_ + 255) / 256, 256>>>(qkv_w + (size_t)l * 3 * D_ * D_,
                                                    wqt + (size_t)l * 3 * D_ * D_, 3 * D_, D_);
        k_cvt_w<<<(D_ * D_ + 255) / 256, 256>>>(out_w + (size_t)l * D_ * D_,
                                                wot + (size_t)l * D_ * D_, D_, D_);
        k_cvt_w<<<(FF_ * D_ + 255) / 256, 256>>>(ff_w1 + (size_t)l * FF_ * D_,
                                                 w1t + (size_t)l * FF_ * D_, FF_, D_);
        k_cvt_w<<<(D_ * FF_ + 255) / 256, 256>>>(ff_w2 + (size_t)l * D_ * FF_,
                                                 w2t + (size_t)l * D_ * FF_, D_, FF_);
    }
    k_cvt_w<<<(V_ * D_ + 255) / 256, 256>>>(head_w, wht, V_, D_);

    k_embed<<<(M_ * D_ + 255) / 256, 256>>>(tokens, types, tok_emb, type_emb, pos_emb);
    k_maskprep<<<1, 32>>>(tokens, attn_mask);

    for (int l = 0; l < NL_; l++) {
        size_t wq_off = (size_t)l * 3 * D_ * D_;
        size_t wo_off = (size_t)l * D_ * D_;
        size_t w1_off = (size_t)l * FF_ * D_;
        size_t w2_off = (size_t)l * D_ * FF_;

        k_ln_t<<<M_, 256>>>(x, ln1_s + l * D_, ln1_b + l * D_, ht);
        gemm_t(ht, wqt + wq_off, qkv, nullptr, 3 * D_, D_, 0, nullptr, nullptr, false);
        k_attn<<<dim3(L_ / 64, B_ * H_), 256, ATTN_SMEM_>>>(qkv);
        gemm_t(yt, wot + wo_off, x, nullptr, D_, D_, 0, nullptr, x, false);
        k_ln_t<<<M_, 256>>>(x, ln2_s + l * D_, ln2_b + l * D_, ht);
        gemm_t(ht, w1t + w1_off, nullptr, ft, FF_, D_, FF_, ff_b1 + l * FF_, nullptr, true);
        gemm_t(ft, w2t + w2_off, x, nullptr, D_, FF_, 0, ff_b2 + l * D_, x, false);
    }
    k_ln_t<<<M_, 256>>>(x, lnf_s, lnf_b, ht);
    gemm_t(ht, wht, out, nullptr, V_, D_, 0, nullptr, nullptr, false);
}